// round 9
// baseline (speedup 1.0000x reference)
#include <cuda_runtime.h>

#define G_ 4
#define T_ 2048
#define E_ 8
#define D_ 1024
#define C_ 2048
#define NTOK (G_ * T_)

#define NB 148
#define THREADS 1024
#define FILLW 26                      // warps 0..25 fill from t=0; 26..31 special
#define NROUTERW (NB * 6)             // 888 router warps
#define NTOPKB 32                     // blocks 0..31 own one (g,e)
#define NFILL_UNITS (NB * 32)         // every warp eventually fills

#define NTOT ((long long)G_ * T_ * E_ * C_)        // 134217728
#define N4 ((long long)(2 * NTOT / 4))             // 67108864 float4
#define CHUNK_F4 4096                               // 64 KB chunk
#define NCHUNKS ((int)(N4 / CHUNK_F4))              // 16384

__device__ float g_probs[G_ * E_ * T_];   // expert-major probs
__device__ float g_zt[NTOK];              // per-token z partials
__device__ int   g_router_done;
__device__ int   g_fill_done;

__global__ void init_kernel() {
    g_router_done = 0;
    g_fill_done = 0;
}

__device__ __forceinline__ void spin_ge(volatile int* p, int target) {
    while (*p < target) __nanosleep(64);
}

__device__ __forceinline__ void bar192() {
    asm volatile("bar.sync 1, 192;" ::: "memory");
}

// Static fill: block B owns chunks {B, B+148, ...}; within a chunk each warp
// writes its fixed thread-stripes (r5's block-interleaved pattern => ~148
// chip-wide write streams), but with NO syncthreads and NO atomics in the
// loop. One no-return RED per warp at the end.
__device__ __forceinline__ void warp_fill(float4* __restrict__ out4,
                                          int B, int tid) {
    const float4 z = make_float4(0.f, 0.f, 0.f, 0.f);
    for (int c = B; c < NCHUNKS; c += NB) {
        long long base = (long long)c * CHUNK_F4 + tid;
        #pragma unroll
        for (int i = 0; i < CHUNK_F4 / THREADS; i++)   // 4 STG.128 per thread
            out4[base + i * THREADS] = z;
    }
    __threadfence();
    if ((tid & 31) == 0) atomicAdd(&g_fill_done, 1);   // result unused -> RED
}

__global__ void __launch_bounds__(THREADS, 1)
fused_kernel(const float* __restrict__ x,
             const float* __restrict__ W,
             const float* __restrict__ b,
             float* __restrict__ out) {
    __shared__ __align__(16) union {
        struct { float sW[E_ * D_]; float sb[E_]; } r;              // 32 KB
        struct { unsigned long long keys[T_]; float red[256]; } t;  // 17 KB
    } sm;

    float4* out4 = reinterpret_cast<float4*>(out);
    int warp = threadIdx.x >> 5;
    int lane = threadIdx.x & 31;
    int B = blockIdx.x;

    // ------------------- fill warps: store from t = 0 -------------------
    if (warp < FILLW) {
        warp_fill(out4, B, threadIdx.x);
        return;
    }

    // ------------------- special warps (26..31): router -------------------
    int tid192 = (warp - FILLW) * 32 + lane;     // 0..191

    for (int i = tid192; i < E_ * D_ / 4; i += 192)
        reinterpret_cast<float4*>(sm.r.sW)[i] = reinterpret_cast<const float4*>(W)[i];
    if (tid192 < E_) sm.r.sb[tid192] = b[tid192];
    bar192();

    int rw = B * 6 + (warp - FILLW);             // global router warp id 0..887
    for (int token = rw; token < NTOK; token += NROUTERW) {
        int g = token / T_;
        int t = token % T_;
        const float4* x4 = reinterpret_cast<const float4*>(x + (long long)token * D_);

        float acc[E_];
        #pragma unroll
        for (int e = 0; e < E_; e++) acc[e] = 0.f;

        #pragma unroll
        for (int i = 0; i < D_ / (32 * 4); i++) {    // 8 iterations
            int d4 = i * 32 + lane;
            float4 xv = x4[d4];
            #pragma unroll
            for (int e = 0; e < E_; e++) {
                float4 wv = reinterpret_cast<const float4*>(sm.r.sW + e * D_)[d4];
                acc[e] += xv.x * wv.x + xv.y * wv.y + xv.z * wv.z + xv.w * wv.w;
            }
        }
        #pragma unroll
        for (int o = 16; o > 0; o >>= 1)
            #pragma unroll
            for (int e = 0; e < E_; e++)
                acc[e] += __shfl_xor_sync(0xffffffffu, acc[e], o);

        float m = -1e30f;
        #pragma unroll
        for (int e = 0; e < E_; e++) { acc[e] += sm.r.sb[e]; m = fmaxf(m, acc[e]); }
        float ex[E_], s = 0.f;
        #pragma unroll
        for (int e = 0; e < E_; e++) { ex[e] = expf(acc[e] - m); s += ex[e]; }
        float inv = 1.f / s;
        float lse = m + logf(s);

        if (lane < E_)
            g_probs[(g * E_ + lane) * T_ + t] = ex[lane] * inv;
        if (lane == 0) {
            float zt = 0.f;
            #pragma unroll
            for (int e = 0; e < E_; e++) {
                float ls = acc[e] - lse;
                zt += ls * ls;
            }
            g_zt[token] = zt;
        }
    }
    __threadfence();
    if (lane == 0) atomicAdd(&g_router_done, 1);     // RED

    // ------------- non-topk blocks: special warps backfill their stripes -------------
    if (B >= NTOPKB) {
        warp_fill(out4, B, threadIdx.x);
        return;
    }

    // ------- topk blocks (0..31): sort -> zloss -> backfill -> wait -> scatter -------
    int ge = B;                // 0..31
    int e = ge & 7;
    int g = ge >> 3;

    if (tid192 == 0) spin_ge(&g_router_done, NROUTERW);
    bar192();                  // also: all 6 warps done reading sW before keys overwrite
    __threadfence();

    const float* p = g_probs + (long long)ge * T_;
    for (int t = tid192; t < T_; t += 192) {
        unsigned int pb = __float_as_uint(p[t]);   // probs > 0 -> bits monotonic
        sm.t.keys[t] = ((unsigned long long)pb << 32) | (unsigned int)(~t);
    }
    bar192();

    // bitonic sort, descending: prob desc, index asc on ties (matches lax.top_k)
    for (int k = 2; k <= T_; k <<= 1) {
        for (int j = k >> 1; j > 0; j >>= 1) {
            for (int i = tid192; i < T_; i += 192) {
                int ixj = i ^ j;
                if (ixj > i) {
                    bool desc = ((i & k) == 0);
                    unsigned long long a = sm.t.keys[i], c = sm.t.keys[ixj];
                    if (desc ? (a < c) : (a > c)) { sm.t.keys[i] = c; sm.t.keys[ixj] = a; }
                }
            }
            bar192();
        }
    }

    // block 0: z-loss reduction (192 partials padded to 256: power-of-two tree)
    if (ge == 0) {
        float acc = 0.f;
        for (int i = tid192; i < NTOK; i += 192)
            acc += g_zt[i];
        sm.t.red[tid192] = acc;
        if (tid192 < 64) sm.t.red[192 + tid192] = 0.f;
        bar192();
        for (int o = 128; o > 0; o >>= 1) {
            if (tid192 < o) sm.t.red[tid192] += sm.t.red[tid192 + o];
            bar192();
        }
        if (tid192 == 0)
            out[2 * NTOT] = sm.t.red[0] / (float)(G_ * T_ * E_);  // beyond fill range
    }

    // backfill this warp's static stripes (touches no smem; keys preserved)
    warp_fill(out4, B, threadIdx.x);

    // wait for the entire fill, then scatter the nonzeros
    if (tid192 == 0) spin_ge(&g_fill_done, NFILL_UNITS);
    bar192();
    __threadfence();

    const int caps[E_] = {512, 512, 256, 256, 128, 128, 128, 128};
    int cap = caps[e];
    for (int r = tid192; r < cap; r += 192) {
        unsigned long long key = sm.t.keys[r];
        float gate = __uint_as_float((unsigned int)(key >> 32));
        int tok = (int)(~(unsigned int)(key & 0xffffffffu));
        long long off = (((long long)g * T_ + tok) * E_ + e) * C_ + r;
        out[off]        = 1.0f;   // dispatch_mask
        out[NTOT + off] = gate;   // combine_array
    }
}

extern "C" void kernel_launch(void* const* d_in, const int* in_sizes, int n_in,
                              void* d_out, int out_size) {
    const float* x = (const float*)d_in[0];   // token_inputs [G,T,D]
    const float* W = (const float*)d_in[1];   // [E,D]
    const float* b = (const float*)d_in[2];   // [E]
    float* out = (float*)d_out;

    init_kernel<<<1, 1>>>();
    fused_kernel<<<NB, THREADS>>>(x, W, b, out);
}

// round 10
// speedup vs baseline: 1.6434x; 1.6434x over previous
#include <cuda_runtime.h>

#define G_ 4
#define T_ 2048
#define E_ 8
#define D_ 1024
#define C_ 2048
#define NTOK (G_ * T_)
#define NTOT ((long long)G_ * T_ * E_ * C_)

__device__ float g_probs[G_ * E_ * T_];   // expert-major probs
__device__ float g_zt[NTOK];              // per-token z partials
__device__ float g_zsum;                  // reduced sum (written by topk)
__device__ int   g_tok [G_ * E_ * C_];    // rank table: token index or -1
__device__ float g_gate[G_ * E_ * C_];    // rank table: gate value

// ---------------------------------------------------------------------------
// Kernel 1: router. 256 threads = 8 warps; each warp owns TWO tokens so every
// LDS.128 of W feeds 2 tokens (halves smem traffic) and ILP doubles.
// W staged in smem once per block.
// ---------------------------------------------------------------------------
__global__ void router_kernel(const float* __restrict__ x,
                              const float* __restrict__ W,
                              const float* __restrict__ b) {
    __shared__ float sW[E_ * D_];   // 32 KB
    __shared__ float sb[E_];

    for (int i = threadIdx.x; i < E_ * D_ / 4; i += blockDim.x)
        reinterpret_cast<float4*>(sW)[i] = reinterpret_cast<const float4*>(W)[i];
    if (threadIdx.x < E_) sb[threadIdx.x] = b[threadIdx.x];
    __syncthreads();

    int warp = threadIdx.x >> 5;
    int lane = threadIdx.x & 31;
    int t0 = blockIdx.x * 16 + warp * 2;     // block covers 16 consecutive tokens
    int t1 = t0 + 1;                          // same g (16 | 2048)
    int g = t0 / T_;
    int tt0 = t0 % T_, tt1 = t1 % T_;

    const float4* x4a = reinterpret_cast<const float4*>(x + (long long)t0 * D_);
    const float4* x4b = reinterpret_cast<const float4*>(x + (long long)t1 * D_);

    float acc0[E_], acc1[E_];
    #pragma unroll
    for (int e = 0; e < E_; e++) { acc0[e] = 0.f; acc1[e] = 0.f; }

    #pragma unroll
    for (int i = 0; i < D_ / (32 * 4); i++) {      // 8 iterations
        int d4 = i * 32 + lane;
        float4 xv0 = x4a[d4];
        float4 xv1 = x4b[d4];
        #pragma unroll
        for (int e = 0; e < E_; e++) {
            float4 wv = reinterpret_cast<const float4*>(sW + e * D_)[d4];
            acc0[e] += xv0.x * wv.x + xv0.y * wv.y + xv0.z * wv.z + xv0.w * wv.w;
            acc1[e] += xv1.x * wv.x + xv1.y * wv.y + xv1.z * wv.z + xv1.w * wv.w;
        }
    }
    #pragma unroll
    for (int o = 16; o > 0; o >>= 1) {
        #pragma unroll
        for (int e = 0; e < E_; e++) {
            acc0[e] += __shfl_xor_sync(0xffffffffu, acc0[e], o);
            acc1[e] += __shfl_xor_sync(0xffffffffu, acc1[e], o);
        }
    }

    // all lanes hold all logits for both tokens
    float m0 = -1e30f, m1 = -1e30f;
    #pragma unroll
    for (int e = 0; e < E_; e++) {
        acc0[e] += sb[e]; acc1[e] += sb[e];
        m0 = fmaxf(m0, acc0[e]); m1 = fmaxf(m1, acc1[e]);
    }
    float ex0[E_], ex1[E_], s0 = 0.f, s1 = 0.f;
    #pragma unroll
    for (int e = 0; e < E_; e++) {
        ex0[e] = expf(acc0[e] - m0); s0 += ex0[e];
        ex1[e] = expf(acc1[e] - m1); s1 += ex1[e];
    }
    float inv0 = 1.f / s0, inv1 = 1.f / s1;
    float lse0 = m0 + logf(s0), lse1 = m1 + logf(s1);

    if (lane < E_)
        g_probs[(g * E_ + lane) * T_ + tt0] = ex0[lane] * inv0;
    else if (lane < 2 * E_)
        g_probs[(g * E_ + (lane - E_)) * T_ + tt1] = ex1[lane - E_] * inv1;

    if (lane == 0) {
        float z0 = 0.f, z1 = 0.f;
        #pragma unroll
        for (int e = 0; e < E_; e++) {
            float a = acc0[e] - lse0, c = acc1[e] - lse1;
            z0 += a * a; z1 += c * c;
        }
        g_zt[t0] = z0;
        g_zt[t1] = z1;
    }
}

// ---------------------------------------------------------------------------
// Kernel 2: per-(g,e) top-cap via in-shared bitonic sort of packed keys
// (prob_bits << 32) | ~idx -> descending gives prob desc, idx asc on ties
// (matches jax.lax.top_k). Emits compact rank tables. Block 0 also reduces z.
// ---------------------------------------------------------------------------
__global__ void topk_kernel() {
    __shared__ unsigned long long s[T_];   // 16 KB

    int ge = blockIdx.x;                   // 0..31
    int e = ge % E_;

    const float* p = g_probs + (long long)ge * T_;
    for (int t = threadIdx.x; t < T_; t += blockDim.x) {
        unsigned int pb = __float_as_uint(p[t]);
        s[t] = ((unsigned long long)pb << 32) | (unsigned int)(~t);
    }
    __syncthreads();

    for (int k = 2; k <= T_; k <<= 1) {
        for (int j = k >> 1; j > 0; j >>= 1) {
            for (int i = threadIdx.x; i < T_; i += blockDim.x) {
                int ixj = i ^ j;
                if (ixj > i) {
                    bool desc = ((i & k) == 0);
                    unsigned long long a = s[i], c = s[ixj];
                    if (desc ? (a < c) : (a > c)) { s[i] = c; s[ixj] = a; }
                }
            }
            __syncthreads();
        }
    }

    const int caps[E_] = {512, 512, 256, 256, 128, 128, 128, 128};
    int cap = caps[e];

    for (int r = threadIdx.x; r < C_; r += blockDim.x) {
        if (r < cap) {
            unsigned long long key = s[r];
            g_gate[ge * C_ + r] = __uint_as_float((unsigned int)(key >> 32));
            g_tok [ge * C_ + r] = (int)(~(unsigned int)(key & 0xffffffffu));
        } else {
            g_gate[ge * C_ + r] = 0.f;
            g_tok [ge * C_ + r] = -1;
        }
    }

    if (blockIdx.x == 0) {
        __syncthreads();
        __shared__ float red[1024];
        float acc = 0.f;
        for (int i = threadIdx.x; i < NTOK; i += 1024)
            acc += g_zt[i];
        red[threadIdx.x] = acc;
        __syncthreads();
        for (int o = 512; o > 0; o >>= 1) {
            if (threadIdx.x < o) red[threadIdx.x] += red[threadIdx.x + o];
            __syncthreads();
        }
        if (threadIdx.x == 0) g_zsum = red[0];
    }
}

// ---------------------------------------------------------------------------
// Kernel 3: fused materialize — entire 1.07 GB output in one pass.
// Block = (g, e, c-half, 16-token chunk); thread owns 4 consecutive c
// (table slice in registers, loaded ONCE per 16 rows) and writes 16 rows of
// dispatch + combine via STG.128. grid = 32*2*128 = 8192, 256 threads.
// ---------------------------------------------------------------------------
__global__ void materialize_kernel(float* __restrict__ out) {
    int B = blockIdx.x;
    int tch   = B & 127;          // token chunk: t in [tch*16, tch*16+16)
    int rest  = B >> 7;
    int chalf = rest & 1;         // which half of C
    int ge    = rest >> 1;        // 0..31
    int e = ge & 7;
    int g = ge >> 3;

    int c4 = chalf * 256 + threadIdx.x;          // float4 index along C
    int4   tok4  = reinterpret_cast<const int4*  >(g_tok )[ge * (C_ / 4) + c4];
    float4 gate4 = reinterpret_cast<const float4*>(g_gate)[ge * (C_ / 4) + c4];

    const long long NTOT4 = NTOT / 4;
    float4* out4 = reinterpret_cast<float4*>(out);

    int tbase = tch * 16;
    #pragma unroll
    for (int i = 0; i < 16; i++) {
        int t = tbase + i;
        long long off = (((long long)g * T_ + t) * E_ + e) * (C_ / 4) + c4;
        float4 d, c;
        d.x = (tok4.x == t) ? 1.f : 0.f;  c.x = (tok4.x == t) ? gate4.x : 0.f;
        d.y = (tok4.y == t) ? 1.f : 0.f;  c.y = (tok4.y == t) ? gate4.y : 0.f;
        d.z = (tok4.z == t) ? 1.f : 0.f;  c.z = (tok4.z == t) ? gate4.z : 0.f;
        d.w = (tok4.w == t) ? 1.f : 0.f;  c.w = (tok4.w == t) ? gate4.w : 0.f;
        out4[off]         = d;   // dispatch_mask
        out4[off + NTOT4] = c;   // combine_array
    }

    if (B == 0 && threadIdx.x == 0)
        out[2 * NTOT] = g_zsum / (float)(G_ * T_ * E_);   // router_z_loss
}

extern "C" void kernel_launch(void* const* d_in, const int* in_sizes, int n_in,
                              void* d_out, int out_size) {
    const float* x = (const float*)d_in[0];   // token_inputs [G,T,D]
    const float* W = (const float*)d_in[1];   // [E,D]
    const float* b = (const float*)d_in[2];   // [E]
    float* out = (float*)d_out;

    router_kernel<<<NTOK / 16, 256>>>(x, W, b);
    topk_kernel<<<G_ * E_, 1024>>>();
    materialize_kernel<<<G_ * E_ * 2 * (T_ / 16), 256>>>(out);
}